// round 8
// baseline (speedup 1.0000x reference)
#include <cuda_runtime.h>
#include <cstdint>

// Problem shape (fixed by reference)
static constexpr int B_ = 8, M_ = 4096, N_ = 1024, D_ = 1024;
static constexpr int ROWS = B_ * M_;            // 32768 LN rows
static constexpr int TM = 128, TN = 128;        // CTA tile
static constexpr int KC = 32;                   // K per chunk
static constexpr int NCHUNK = N_ / KC;          // 32
static constexpr int RB = ROWS / TM;            // 256 row blocks
static constexpr int NB = D_ / TN;              // 8 col blocks

// SMEM: 3 stages x (A 4096 words + B 4096 words)
static constexpr int A_CHUNK_WORDS = TM * KC;   // 4096
static constexpr int B_CHUNK_WORDS = KC * TN;   // 4096
static constexpr int STAGE_WORDS = A_CHUNK_WORDS + B_CHUNK_WORDS;  // 8192
static constexpr int NSTAGE = 3;
static constexpr int SMEM_DYN = NSTAGE * STAGE_WORDS * 4;          // 98304 B

// Device-global scratch (no allocation APIs)
__device__ float g_mean[ROWS];
__device__ float g_rstd[ROWS];
// A fragments: [rb 256][c 32][mt 8][ks 4][lane 32][reg 4]  (tf32 words)
__device__ uint32_t g_afrag[(size_t)RB * NCHUNK * A_CHUNK_WORDS];
// B fragments: [nb 8][c 32][nt 16][ks 4][lane 32][reg 2]
__device__ uint32_t g_bfrag[(size_t)NB * NCHUNK * B_CHUNK_WORDS];

// ---------------------------------------------------------------- helpers ---
__device__ __forceinline__ uint32_t f2tf32(float f) {
    uint32_t r;
    asm("cvt.rna.tf32.f32 %0, %1;" : "=r"(r) : "f"(f));
    return r;
}

__device__ __forceinline__ uint32_t smem_u32(const void* p) {
    uint32_t a;
    asm("{ .reg .u64 t; cvta.to.shared.u64 t, %1; cvt.u32.u64 %0, t; }" : "=r"(a) : "l"(p));
    return a;
}

__device__ __forceinline__ void mma_tf32(float* c, const uint32_t* a, const uint32_t* b) {
    asm volatile(
        "mma.sync.aligned.m16n8k8.row.col.f32.tf32.tf32.f32 "
        "{%0,%1,%2,%3}, {%4,%5,%6,%7}, {%8,%9}, {%0,%1,%2,%3};"
        : "+f"(c[0]), "+f"(c[1]), "+f"(c[2]), "+f"(c[3])
        : "r"(a[0]), "r"(a[1]), "r"(a[2]), "r"(a[3]), "r"(b[0]), "r"(b[1]));
}

__device__ __forceinline__ void cpasync16(uint32_t smem_addr, const void* gptr) {
    asm volatile("cp.async.cg.shared.global [%0], [%1], 16;"
                 :: "r"(smem_addr), "l"(gptr) : "memory");
}
#define CP_COMMIT()  asm volatile("cp.async.commit_group;" ::: "memory")
#define CP_WAIT(n)   asm volatile("cp.async.wait_group %0;" :: "n"(n) : "memory")

#define LDS128(r0, r1, r2, r3, addr) \
    asm volatile("ld.shared.v4.b32 {%0,%1,%2,%3}, [%4];" \
                 : "=r"(r0), "=r"(r1), "=r"(r2), "=r"(r3) : "r"(addr))
#define LDS64(r0, r1, addr) \
    asm volatile("ld.shared.v2.b32 {%0,%1}, [%2];" : "=r"(r0), "=r"(r1) : "r"(addr))

// --------------------------------------------------------- LN stats kernel ---
__global__ void __launch_bounds__(256) ln_stats_kernel(const float* __restrict__ x) {
    const int row = blockIdx.x;
    float4 v = reinterpret_cast<const float4*>(x + (size_t)row * N_)[threadIdx.x];
    float s  = v.x + v.y + v.z + v.w;
    float ss = v.x * v.x + v.y * v.y + v.z * v.z + v.w * v.w;
#pragma unroll
    for (int o = 16; o > 0; o >>= 1) {
        s  += __shfl_xor_sync(0xffffffffu, s, o);
        ss += __shfl_xor_sync(0xffffffffu, ss, o);
    }
    __shared__ float sh[16];
    const int wid = threadIdx.x >> 5, lid = threadIdx.x & 31;
    if (lid == 0) { sh[wid] = s; sh[8 + wid] = ss; }
    __syncthreads();
    if (threadIdx.x == 0) {
        float ts = 0.f, tss = 0.f;
#pragma unroll
        for (int i = 0; i < 8; i++) { ts += sh[i]; tss += sh[8 + i]; }
        const float m   = ts * (1.0f / N_);
        const float var = tss * (1.0f / N_) - m * m;
        g_mean[row] = m;
        g_rstd[row] = rsqrtf(var + 1e-5f);
    }
}

// ------------------------------------------- LN -> tf32 A-fragment kernel ---
// Fragment mapping (verified on HW by the R5 passing kernel):
//   reg0 = (row g,   k t)   reg1 = (row g+8, k t)
//   reg2 = (row g,   k t+4) reg3 = (row g+8, k t+4)   g=lane>>2, t=lane&3
__global__ void __launch_bounds__(256) ln_frag_kernel(
    const float* __restrict__ x, const float* __restrict__ gamma,
    const float* __restrict__ beta) {
    const int c = blockIdx.x, rb = blockIdx.y;
    const int tid = threadIdx.x, mt = tid >> 5, lane = tid & 31;
    const int g = lane >> 2, t = lane & 3;
    const int m0 = rb * TM + mt * 16 + g, m1 = m0 + 8;
    const float mn0 = g_mean[m0], rs0 = g_rstd[m0];
    const float mn1 = g_mean[m1], rs1 = g_rstd[m1];
    const float* x0 = x + (size_t)m0 * N_ + c * KC;
    const float* x1 = x + (size_t)m1 * N_ + c * KC;
    uint32_t* dst = g_afrag + ((size_t)(rb * NCHUNK + c) * 32 + mt * 4) * 128 + lane * 4;
#pragma unroll
    for (int ks = 0; ks < 4; ks++) {
        const int k0 = ks * 8 + t, k1 = k0 + 4;
        const float ga0 = gamma[c * KC + k0], be0 = beta[c * KC + k0];
        const float ga1 = gamma[c * KC + k1], be1 = beta[c * KC + k1];
        uint4 o;
        o.x = f2tf32((x0[k0] - mn0) * rs0 * ga0 + be0);
        o.y = f2tf32((x1[k0] - mn1) * rs1 * ga0 + be0);
        o.z = f2tf32((x0[k1] - mn0) * rs0 * ga1 + be1);
        o.w = f2tf32((x1[k1] - mn1) * rs1 * ga1 + be1);
        *reinterpret_cast<uint4*>(dst + ks * 128) = o;
    }
}

// --------------------------------------------- w -> tf32 B-fragment kernel ---
//   reg0 = (k t, n g)   reg1 = (k t+4, n g)
__global__ void __launch_bounds__(256) w_frag_kernel(const float* __restrict__ w) {
    const int c = blockIdx.x, nb = blockIdx.y;
    const int tid = threadIdx.x, lane = tid & 31;
    const int ks = (tid >> 5) & 3, half = tid >> 7;
    const int g = lane >> 2, t = lane & 3;
    const int k0 = c * KC + ks * 8 + t;
#pragma unroll
    for (int h = 0; h < 8; h++) {
        const int nt = half * 8 + h;
        const int n = nb * TN + nt * 8 + g;
        uint2 o;
        o.x = f2tf32(w[(size_t)k0 * D_ + n]);
        o.y = f2tf32(w[(size_t)(k0 + 4) * D_ + n]);
        *reinterpret_cast<uint2*>(
            g_bfrag + ((size_t)(nb * NCHUNK + c) * 16 + nt) * 256 + ks * 64 + lane * 2) = o;
    }
}

// ------------------------------------------------------------- GEMM kernel ---
__global__ void __launch_bounds__(256, 2) ln_gemm_kernel(
    const float* __restrict__ bias, float* __restrict__ out) {
    extern __shared__ uint32_t smw[];
    const uint32_t sbase = smem_u32(smw);
    const int tid = threadIdx.x, wid = tid >> 5, lane = tid & 31;
    const int bx = blockIdx.x, by = blockIdx.y;
    const int wm = wid >> 2, wn = wid & 3;

    const uint4* gA = reinterpret_cast<const uint4*>(g_afrag) + (size_t)by * NCHUNK * 1024;
    const uint4* gB = reinterpret_cast<const uint4*>(g_bfrag) + (size_t)bx * NCHUNK * 1024;

    // issue one chunk's copies into a stage (8 x 16B per thread) + commit
    auto issue = [&](int chunk, int stage) {
        const uint32_t dstA = sbase + (uint32_t)stage * (STAGE_WORDS * 4) + tid * 16;
        const uint4* srcA = gA + chunk * 1024 + tid;
#pragma unroll
        for (int i = 0; i < 4; i++) cpasync16(dstA + i * 4096, srcA + i * 256);
        const uint32_t dstB = dstA + A_CHUNK_WORDS * 4;
        const uint4* srcB = gB + chunk * 1024 + tid;
#pragma unroll
        for (int i = 0; i < 4; i++) cpasync16(dstB + i * 4096, srcB + i * 256);
        CP_COMMIT();
    };

    issue(0, 0);
    issue(1, 1);

    float acc[4][4][4];
#pragma unroll
    for (int i = 0; i < 4; i++)
#pragma unroll
        for (int j = 0; j < 4; j++)
#pragma unroll
            for (int r = 0; r < 4; r++) acc[i][j][r] = 0.f;

    for (int c = 0; c < NCHUNK; c++) {
        // chunk c complete when <=1 (or 0 at the tail) groups remain in flight
        if (c < NCHUNK - 2) { CP_WAIT(1); } else { CP_WAIT(0); }
        __syncthreads();   // also guarantees everyone finished reading stage (c-1)%3
        if (c + 2 < NCHUNK) issue(c + 2, (c + 2) % NSTAGE);

        const uint32_t Asw = sbase + (uint32_t)(c % NSTAGE) * (STAGE_WORDS * 4);
        const uint32_t Bsw = Asw + A_CHUNK_WORDS * 4;

#pragma unroll
        for (int ks = 0; ks < 4; ks++) {
            uint32_t afr[4][4];
#pragma unroll
            for (int i = 0; i < 4; i++)
                LDS128(afr[i][0], afr[i][1], afr[i][2], afr[i][3],
                       Asw + (uint32_t)(((wm * 4 + i) * 4 + ks) * 512 + lane * 16));
            uint32_t bfr[4][2];
#pragma unroll
            for (int j = 0; j < 4; j++)
                LDS64(bfr[j][0], bfr[j][1],
                      Bsw + (uint32_t)(((wn * 4 + j) * 4 + ks) * 256 + lane * 8));
#pragma unroll
            for (int i = 0; i < 4; i++)
#pragma unroll
                for (int j = 0; j < 4; j++)
                    mma_tf32(acc[i][j], afr[i], bfr[j]);
        }
    }

    // ---- epilogue: acc + bias -> gmem (layout identical to R5 passing kernel)
    const int d0 = bx * TN;
    const int row_base = by * TM;
    const int g = lane >> 2;
    const int t = lane & 3;
    float2 bb[4];
#pragma unroll
    for (int j = 0; j < 4; j++)
        bb[j] = *reinterpret_cast<const float2*>(bias + d0 + wn * 32 + j * 8 + 2 * t);
#pragma unroll
    for (int i = 0; i < 4; i++) {
        const int r0 = row_base + wm * 64 + i * 16 + g;
#pragma unroll
        for (int j = 0; j < 4; j++) {
            const int col = d0 + wn * 32 + j * 8 + 2 * t;
            float2 o0, o1;
            o0.x = acc[i][j][0] + bb[j].x;
            o0.y = acc[i][j][1] + bb[j].y;
            o1.x = acc[i][j][2] + bb[j].x;
            o1.y = acc[i][j][3] + bb[j].y;
            *reinterpret_cast<float2*>(out + (size_t)r0 * D_ + col) = o0;
            *reinterpret_cast<float2*>(out + (size_t)(r0 + 8) * D_ + col) = o1;
        }
    }
}

// ------------------------------------------------------------------ launch ---
extern "C" void kernel_launch(void* const* d_in, const int* in_sizes, int n_in,
                              void* d_out, int out_size) {
    const float* x     = (const float*)d_in[0];
    const float* w     = (const float*)d_in[1];
    const float* b     = (const float*)d_in[2];
    const float* gamma = (const float*)d_in[3];
    const float* beta  = (const float*)d_in[4];
    float* out = (float*)d_out;

    cudaFuncSetAttribute(ln_gemm_kernel, cudaFuncAttributeMaxDynamicSharedMemorySize, SMEM_DYN);

    ln_stats_kernel<<<ROWS, 256>>>(x);
    w_frag_kernel<<<dim3(NCHUNK, NB), 256>>>(w);
    ln_frag_kernel<<<dim3(NCHUNK, RB), 256>>>(x, gamma, beta);
    ln_gemm_kernel<<<dim3(NB, RB), 256, SMEM_DYN>>>(b, out);
}

// round 10
// speedup vs baseline: 1.0383x; 1.0383x over previous
#include <cuda_runtime.h>
#include <cstdint>

// Problem shape (fixed by reference)
static constexpr int B_ = 8, M_ = 4096, N_ = 1024, D_ = 1024;
static constexpr int ROWS = B_ * M_;            // 32768 LN rows
static constexpr int TM = 128, TN = 256;        // CTA tile (new: TN=256)
static constexpr int KC = 32;                   // K per chunk
static constexpr int NCHUNK = N_ / KC;          // 32
static constexpr int RB = ROWS / TM;            // 256 row blocks
static constexpr int NB = D_ / TN;              // 4 col blocks

// Chunk sizes (tf32 words)
static constexpr int A_CHUNK_WORDS = TM * KC;   // 4096  (16 KB)
static constexpr int B_CHUNK_WORDS = KC * TN;   // 8192  (32 KB)
static constexpr int STAGE_BYTES = (A_CHUNK_WORDS + B_CHUNK_WORDS) * 4;  // 49152
static constexpr int NSTAGE = 4;
static constexpr int SMEM_DYN = NSTAGE * STAGE_BYTES;                    // 196608

// Device-global fragment scratch (no allocation APIs)
// A fragments: [rb 256][c 32][mt 8][ks 4][lane 32][reg 4]
__device__ uint32_t g_afrag[(size_t)RB * NCHUNK * A_CHUNK_WORDS];
// B fragments: [nb 4][c 32][nt 32][ksp 2][lane 32][4 words]
//   uint4 = { b(ks=2p, t), b(ks=2p, t+4), b(ks=2p+1, t), b(ks=2p+1, t+4) }
__device__ uint32_t g_bfrag[(size_t)NB * NCHUNK * B_CHUNK_WORDS];

// ---------------------------------------------------------------- helpers ---
__device__ __forceinline__ uint32_t f2tf32(float f) {
    uint32_t r;
    asm("cvt.rna.tf32.f32 %0, %1;" : "=r"(r) : "f"(f));
    return r;
}

__device__ __forceinline__ uint32_t smem_u32(const void* p) {
    uint32_t a;
    asm("{ .reg .u64 t; cvta.to.shared.u64 t, %1; cvt.u32.u64 %0, t; }" : "=r"(a) : "l"(p));
    return a;
}

__device__ __forceinline__ void mma_tf32(float* c, const uint32_t* a,
                                         uint32_t b0, uint32_t b1) {
    asm volatile(
        "mma.sync.aligned.m16n8k8.row.col.f32.tf32.tf32.f32 "
        "{%0,%1,%2,%3}, {%4,%5,%6,%7}, {%8,%9}, {%0,%1,%2,%3};"
        : "+f"(c[0]), "+f"(c[1]), "+f"(c[2]), "+f"(c[3])
        : "r"(a[0]), "r"(a[1]), "r"(a[2]), "r"(a[3]), "r"(b0), "r"(b1));
}

__device__ __forceinline__ void cpasync16(uint32_t smem_addr, const void* gptr) {
    asm volatile("cp.async.cg.shared.global [%0], [%1], 16;"
                 :: "r"(smem_addr), "l"(gptr) : "memory");
}
#define CP_COMMIT()  asm volatile("cp.async.commit_group;" ::: "memory")
#define CP_WAIT(n)   asm volatile("cp.async.wait_group %0;" :: "n"(n) : "memory")

#define LDS128(r0, r1, r2, r3, addr) \
    asm volatile("ld.shared.v4.b32 {%0,%1,%2,%3}, [%4];" \
                 : "=r"(r0), "=r"(r1), "=r"(r2), "=r"(r3) : "r"(addr))

// -------------------------------- fused stats + LN -> A-fragment kernel ----
// One block = one 16-row mtile. Stages the 16x1024 x-slab in SMEM (read x ONCE),
// computes per-row mean/rstd, then emits fragment-layout tf32 (coalesced uint4).
// Fragment mapping (HW-verified by the R5/R8 passing kernels):
//   reg0=(row g, k t) reg1=(row g+8, k t) reg2=(row g, k t+4) reg3=(row g+8, k t+4)
static constexpr int XS_STRIDE = 1032;   // floats per row (1024 + 8 pad)
__global__ void __launch_bounds__(256) ln_prep_kernel(
    const float* __restrict__ x, const float* __restrict__ gamma,
    const float* __restrict__ beta) {
    extern __shared__ float sprep[];          // [16][1032] x + [1024] g + [1024] b
    float* xs = sprep;
    float* sg = sprep + 16 * XS_STRIDE;
    float* sb = sg + 1024;
    __shared__ float smean[16], srstd[16];

    const int blk = blockIdx.x;               // 0..2047 ; rb=blk>>3, mt=blk&7
    const int tid = threadIdx.x, w = tid >> 5, lane = tid & 31;

    // phase 1: coalesced load of 16 rows + gamma/beta
    {
        const float4* x4 = reinterpret_cast<const float4*>(x) + (size_t)blk * 16 * 256;
#pragma unroll
        for (int i = 0; i < 16; i++) {
            const int idx = i * 256 + tid;
            const int row = idx >> 8, col4 = idx & 255;
            *reinterpret_cast<float4*>(xs + row * XS_STRIDE + col4 * 4) = x4[row * 256 + col4];
        }
        reinterpret_cast<float4*>(sg)[tid] = reinterpret_cast<const float4*>(gamma)[tid];
        reinterpret_cast<float4*>(sb)[tid] = reinterpret_cast<const float4*>(beta)[tid];
    }
    __syncthreads();

    // phase 2: per-row stats (warp w handles rows 2w, 2w+1)
#pragma unroll
    for (int rr = 0; rr < 2; rr++) {
        const int row = w * 2 + rr;
        float s = 0.f, ss = 0.f;
#pragma unroll
        for (int j = 0; j < 8; j++) {
            const float4 v = *reinterpret_cast<const float4*>(
                xs + row * XS_STRIDE + (lane + j * 32) * 4);
            s  += v.x + v.y + v.z + v.w;
            ss += v.x * v.x + v.y * v.y + v.z * v.z + v.w * v.w;
        }
#pragma unroll
        for (int o = 16; o > 0; o >>= 1) {
            s  += __shfl_xor_sync(0xffffffffu, s, o);
            ss += __shfl_xor_sync(0xffffffffu, ss, o);
        }
        if (lane == 0) {
            const float m = s * (1.0f / N_);
            smean[row] = m;
            srstd[row] = rsqrtf(ss * (1.0f / N_) - m * m + 1e-5f);
        }
    }
    __syncthreads();

    // phase 3: emit fragments (warp w covers 16 (c,ks) combos)
    const int g = lane >> 2, t = lane & 3;
    const float mn0 = smean[g],     rs0 = srstd[g];
    const float mn1 = smean[g + 8], rs1 = srstd[g + 8];
    const float* xr0 = xs + g * XS_STRIDE;
    const float* xr1 = xs + (g + 8) * XS_STRIDE;
    uint4* dst_base = reinterpret_cast<uint4*>(g_afrag) + ((size_t)blk * 128 + lane) ;
#pragma unroll
    for (int i = 0; i < 16; i++) {
        const int c  = (i >> 2) * 8 + w;
        const int ks = i & 3;
        const int k0 = c * KC + ks * 8 + t, k1 = k0 + 4;
        const float ga0 = sg[k0], be0 = sb[k0];
        const float ga1 = sg[k1], be1 = sb[k1];
        uint4 o;
        o.x = f2tf32((xr0[k0] - mn0) * rs0 * ga0 + be0);
        o.y = f2tf32((xr1[k0] - mn1) * rs1 * ga0 + be0);
        o.z = f2tf32((xr0[k1] - mn0) * rs0 * ga1 + be1);
        o.w = f2tf32((xr1[k1] - mn1) * rs1 * ga1 + be1);
        // g_afrag word index = ((rb*32 + c)*32 + mt*4 + ks)*128 + lane*4
        // blk*128 uint4 covers the mtile; within: (c*... ) reorganized:
        // global uint4 idx = ((rb*32+c)*32 + mt*4 + ks)*32 + lane
        const int rb = blk >> 3, mt = blk & 7;
        reinterpret_cast<uint4*>(g_afrag)[
            (((size_t)(rb * 32 + c) * 32) + mt * 4 + ks) * 32 + lane] = o;
    }
    (void)dst_base;
}

// --------------------------------------------- w -> tf32 B-fragment kernel ---
__global__ void __launch_bounds__(256) w_frag_kernel(const float* __restrict__ w) {
    const int c = blockIdx.x, nb = blockIdx.y;
    const int tid = threadIdx.x, wr = tid >> 5, lane = tid & 31;
    const int g = lane >> 2, t = lane & 3;
#pragma unroll
    for (int i = 0; i < 8; i++) {
        const int nt = wr * 4 + (i >> 1);
        const int ksp = i & 1;
        const int n = nb * TN + nt * 8 + g;
        const int kb = c * KC + ksp * 16 + t;
        uint4 o;
        o.x = f2tf32(w[(size_t)kb * D_ + n]);
        o.y = f2tf32(w[(size_t)(kb + 4) * D_ + n]);
        o.z = f2tf32(w[(size_t)(kb + 8) * D_ + n]);
        o.w = f2tf32(w[(size_t)(kb + 12) * D_ + n]);
        reinterpret_cast<uint4*>(g_bfrag)[
            ((size_t)(nb * NCHUNK + c) * 2048) + (nt * 2 + ksp) * 32 + lane] = o;
    }
}

// ------------------------------------------------------------- GEMM kernel ---
// CTA 128x256, 8 warps, warp tile 64x64 (wm=wid>>2 in {0,1}, wn=wid&3 in 0..3).
__global__ void __launch_bounds__(256, 1) ln_gemm_kernel(
    const float* __restrict__ bias, float* __restrict__ out) {
    extern __shared__ uint32_t smw[];
    const uint32_t sbase = smem_u32(smw);
    const int tid = threadIdx.x, wid = tid >> 5, lane = tid & 31;
    const int bx = blockIdx.x, by = blockIdx.y;
    const int wm = wid >> 2, wn = wid & 3;

    const uint4* gA = reinterpret_cast<const uint4*>(g_afrag) + (size_t)by * NCHUNK * 1024;
    const uint4* gB = reinterpret_cast<const uint4*>(g_bfrag) + (size_t)bx * NCHUNK * 2048;

    auto issue = [&](int chunk, int stage) {
        const uint32_t dstA = sbase + (uint32_t)stage * STAGE_BYTES + tid * 16;
        const uint4* srcA = gA + chunk * 1024 + tid;
#pragma unroll
        for (int i = 0; i < 4; i++) cpasync16(dstA + i * 4096, srcA + i * 256);
        const uint32_t dstB = dstA + A_CHUNK_WORDS * 4;
        const uint4* srcB = gB + chunk * 2048 + tid;
#pragma unroll
        for (int i = 0; i < 8; i++) cpasync16(dstB + i * 4096, srcB + i * 256);
        CP_COMMIT();
    };

    issue(0, 0);
    issue(1, 1);
    issue(2, 2);

    float acc[4][8][4];
#pragma unroll
    for (int i = 0; i < 4; i++)
#pragma unroll
        for (int j = 0; j < 8; j++)
#pragma unroll
            for (int r = 0; r < 4; r++) acc[i][j][r] = 0.f;

    for (int c = 0; c < NCHUNK; c++) {
        if (c < NCHUNK - 3)      { CP_WAIT(2); }
        else if (c == NCHUNK - 3){ CP_WAIT(2); }
        else if (c == NCHUNK - 2){ CP_WAIT(1); }
        else                     { CP_WAIT(0); }
        __syncthreads();
        if (c + 3 < NCHUNK) issue(c + 3, (c + 3) & 3);

        const uint32_t Asw = sbase + (uint32_t)(c & 3) * STAGE_BYTES;
        const uint32_t Bsw = Asw + A_CHUNK_WORDS * 4;

#pragma unroll
        for (int ksp = 0; ksp < 2; ksp++) {
            uint32_t bfr[8][4];
#pragma unroll
            for (int j = 0; j < 8; j++)
                LDS128(bfr[j][0], bfr[j][1], bfr[j][2], bfr[j][3],
                       Bsw + (uint32_t)((((wn * 8 + j) * 2 + ksp) * 128 + lane * 4) * 4));
#pragma unroll
            for (int h = 0; h < 2; h++) {
                const int ks = ksp * 2 + h;
                uint32_t afr[4][4];
#pragma unroll
                for (int i = 0; i < 4; i++)
                    LDS128(afr[i][0], afr[i][1], afr[i][2], afr[i][3],
                           Asw + (uint32_t)((((wm * 4 + i) * 4 + ks) * 128 + lane * 4) * 4));
#pragma unroll
                for (int i = 0; i < 4; i++)
#pragma unroll
                    for (int j = 0; j < 8; j++)
                        mma_tf32(acc[i][j], afr[i], bfr[j][2 * h], bfr[j][2 * h + 1]);
            }
        }
    }

    // ---- epilogue: acc + bias -> gmem
    const int d0 = bx * TN;
    const int row_base = by * TM;
    const int g = lane >> 2;
    const int t = lane & 3;
    float2 bb[8];
#pragma unroll
    for (int j = 0; j < 8; j++)
        bb[j] = *reinterpret_cast<const float2*>(bias + d0 + wn * 64 + j * 8 + 2 * t);
#pragma unroll
    for (int i = 0; i < 4; i++) {
        const int r0 = row_base + wm * 64 + i * 16 + g;
#pragma unroll
        for (int j = 0; j < 8; j++) {
            const int col = d0 + wn * 64 + j * 8 + 2 * t;
            float2 o0, o1;
            o0.x = acc[i][j][0] + bb[j].x;
            o0.y = acc[i][j][1] + bb[j].y;
            o1.x = acc[i][j][2] + bb[j].x;
            o1.y = acc[i][j][3] + bb[j].y;
            *reinterpret_cast<float2*>(out + (size_t)r0 * D_ + col) = o0;
            *reinterpret_cast<float2*>(out + (size_t)(r0 + 8) * D_ + col) = o1;
        }
    }
}

// ------------------------------------------------------------------ launch ---
extern "C" void kernel_launch(void* const* d_in, const int* in_sizes, int n_in,
                              void* d_out, int out_size) {
    const float* x     = (const float*)d_in[0];
    const float* w     = (const float*)d_in[1];
    const float* b     = (const float*)d_in[2];
    const float* gamma = (const float*)d_in[3];
    const float* beta  = (const float*)d_in[4];
    float* out = (float*)d_out;

    static constexpr int PREP_SMEM = (16 * XS_STRIDE + 2048) * 4;  // 74240 B
    cudaFuncSetAttribute(ln_prep_kernel, cudaFuncAttributeMaxDynamicSharedMemorySize, PREP_SMEM);
    cudaFuncSetAttribute(ln_gemm_kernel, cudaFuncAttributeMaxDynamicSharedMemorySize, SMEM_DYN);

    w_frag_kernel<<<dim3(NCHUNK, NB), 256>>>(w);
    ln_prep_kernel<<<ROWS / 16, 256, PREP_SMEM>>>(x, gamma, beta);
    ln_gemm_kernel<<<dim3(NB, RB), 256, SMEM_DYN>>>(b, out);
}